// round 3
// baseline (speedup 1.0000x reference)
#include <cuda_runtime.h>

#define N_CELLS   776
#define N_ANCHORS 3
#define N_CH      7
#define N_FLOATS  (N_CELLS * N_ANCHORS * N_CH)   // 16296
#define N_F4      (N_FLOATS / 4)                 // 4074 (exact)
#define SMEM_BYTES (N_FLOATS * sizeof(float))    // 65184
#define CONF_THRESH 0.8f
#define NO_OBJECT   0.5f

__global__ void __launch_bounds__(1024, 1)
yolo_loss_kernel(const float* __restrict__ pred,
                 const float* __restrict__ label,
                 float* __restrict__ out)
{
    extern __shared__ float s[];           // 16296 floats, coalesced-staged pred
    __shared__ float warp_sums[32];

    // ---- coalesced float4 staging: 4074 vectors, 1024 threads -> 4 iters ----
    {
        float4* s4 = reinterpret_cast<float4*>(s);
        const float4* p4 = reinterpret_cast<const float4*>(pred);
        #pragma unroll
        for (int i = threadIdx.x; i < N_F4; i += 1024)
            s4[i] = p4[i];
    }

    // Broadcast label (same address for all threads -> broadcast, cheap)
    const float l0 = label[0], l1 = label[1], l2 = label[2], l3 = label[3];
    const float l4 = label[4], l5 = label[5], l6 = label[6];

    __syncthreads();

    const int cell = threadIdx.x;
    float loss = 0.0f;

    if (cell < N_CELLS) {
        // stride-21 smem reads: 21 coprime with 32 banks -> conflict-free
        float ch[N_ANCHORS][N_CH];
        #pragma unroll
        for (int a = 0; a < N_ANCHORS; a++)
            #pragma unroll
            for (int c = 0; c < N_CH; c++)
                ch[a][c] = s[cell * (N_ANCHORS * N_CH) + a * N_CH + c];

        const float lx0 = l0 - l2 * 0.5f;
        const float ly0 = l1 - l3 * 0.5f;
        const float lx1 = l0 + l2 * 0.5f;
        const float ly1 = l1 + l3 * 0.5f;
        const float area_b = fabsf(l2 * l3);

        float iou_a[N_ANCHORS];
        #pragma unroll
        for (int a = 0; a < N_ANCHORS; a++) {
            const float px = ch[a][0];
            const float py = ch[a][1];
            const float pw = ch[a][2];
            const float ph = ch[a][3];

            const float ax = fmaxf(px - pw * 0.5f, lx0);
            const float ay = fmaxf(py - ph * 0.5f, ly0);
            const float bx = fminf(px + pw * 0.5f, lx1);
            const float by = fminf(py + ph * 0.5f, ly1);

            const float inter = fabsf(fmaxf(bx - ax, 0.0f) * fmaxf(by - ay, 0.0f));
            const float area_a = fabsf(pw * ph);
            iou_a[a] = inter / (area_a + area_b - inter);
        }

        // argmax with first-max tie-break (strict >), select in registers
        float b0 = ch[0][0], b1 = ch[0][1], b4 = ch[0][4], b5 = ch[0][5], b6 = ch[0][6];
        float best = iou_a[0];
        if (iou_a[1] > best) {
            best = iou_a[1];
            b0 = ch[1][0]; b1 = ch[1][1]; b4 = ch[1][4]; b5 = ch[1][5]; b6 = ch[1][6];
        }
        if (iou_a[2] > best) {
            best = iou_a[2];
            b0 = ch[2][0]; b1 = ch[2][1]; b4 = ch[2][4]; b5 = ch[2][5]; b6 = ch[2][6];
        }

        // NOTE: wh_loss intentionally reuses indices 0/1 (x/y) — replicates
        // the reference exactly.
        const float dx = l0 - b0;
        const float dy = l1 - b1;
        const float xy_loss = dx * dx + dy * dy;

        const float sx = sqrtf(l0) - sqrtf(b0);
        const float sy = sqrtf(l1) - sqrtf(b1);
        const float wh_loss = sx * sx + sy * sy;

        const float coord_loss = xy_loss + wh_loss;

        const bool has_obj = b4 > CONF_THRESH;

        const float d5 = l5 - b5;
        const float d6 = l6 - b6;
        const float class_loss = has_obj ? (d5 * d5 + d6 * d6) : 0.0f;

        const float dc = l4 - b4;
        const float conf_sq = dc * dc;
        const float conf_loss = has_obj ? conf_sq : NO_OBJECT * conf_sq;

        loss = coord_loss + class_loss + conf_loss;
    }

    // ---- block reduction: warp shuffle then smem across 32 warps ----
    #pragma unroll
    for (int off = 16; off > 0; off >>= 1)
        loss += __shfl_down_sync(0xFFFFFFFFu, loss, off);

    const int lane = threadIdx.x & 31;
    const int warp = threadIdx.x >> 5;
    if (lane == 0) warp_sums[warp] = loss;
    __syncthreads();

    if (warp == 0) {
        float v = warp_sums[lane];   // exactly 32 warps at blockDim=1024
        #pragma unroll
        for (int off = 16; off > 0; off >>= 1)
            v += __shfl_down_sync(0xFFFFFFFFu, v, off);
        if (lane == 0) out[0] = v;
    }
}

extern "C" void kernel_launch(void* const* d_in, const int* in_sizes, int n_in,
                              void* d_out, int out_size)
{
    const float* pred  = (const float*)d_in[0];
    const float* label = (const float*)d_in[1];
    float* out = (float*)d_out;

    // >48KB dynamic smem requires opting in (host attribute set; graph-legal,
    // no allocation). Deterministic: same call every time.
    cudaFuncSetAttribute(yolo_loss_kernel,
                         cudaFuncAttributeMaxDynamicSharedMemorySize,
                         SMEM_BYTES);

    yolo_loss_kernel<<<1, 1024, SMEM_BYTES>>>(pred, label, out);
}

// round 4
// speedup vs baseline: 1.0258x; 1.0258x over previous
#include <cuda_runtime.h>

#define N_CELLS   776
#define N_ANCHORS 3
#define N_CH      7
#define N_THREADS 800          // 25 warps; threads 776..799 idle
#define N_WARPS   (N_THREADS / 32)
#define CONF_THRESH 0.8f
#define NO_OBJECT   0.5f

__global__ void __launch_bounds__(N_THREADS, 1)
yolo_loss_kernel(const float* __restrict__ pred,
                 const float* __restrict__ label,
                 float* __restrict__ out)
{
    __shared__ float warp_sums[N_WARPS];

    const int cell = threadIdx.x;
    float loss = 0.0f;

    if (cell < N_CELLS) {
        const float* base = pred + cell * (N_ANCHORS * N_CH);

        // Front-batch ALL loads (21 pred + 7 label) so the single L2-latency
        // exposure is paid once with MLP ~28, then compute is register-only.
        float ch[N_ANCHORS][N_CH];
        #pragma unroll
        for (int a = 0; a < N_ANCHORS; a++)
            #pragma unroll
            for (int c = 0; c < N_CH; c++)
                ch[a][c] = base[a * N_CH + c];

        const float l0 = label[0], l1 = label[1], l2 = label[2], l3 = label[3];
        const float l4 = label[4], l5 = label[5], l6 = label[6];

        const float lx0 = l0 - l2 * 0.5f;
        const float ly0 = l1 - l3 * 0.5f;
        const float lx1 = l0 + l2 * 0.5f;
        const float ly1 = l1 + l3 * 0.5f;
        const float area_b = fabsf(l2 * l3);

        float iou_a[N_ANCHORS];
        #pragma unroll
        for (int a = 0; a < N_ANCHORS; a++) {
            const float px = ch[a][0];
            const float py = ch[a][1];
            const float pw = ch[a][2];
            const float ph = ch[a][3];

            const float ax = fmaxf(px - pw * 0.5f, lx0);
            const float ay = fmaxf(py - ph * 0.5f, ly0);
            const float bx = fminf(px + pw * 0.5f, lx1);
            const float by = fminf(py + ph * 0.5f, ly1);

            const float inter = fabsf(fmaxf(bx - ax, 0.0f) * fmaxf(by - ay, 0.0f));
            const float area_a = fabsf(pw * ph);
            iou_a[a] = inter / (area_a + area_b - inter);
        }

        // argmax, first-max tie-break (strict >) — register selects, no gather
        float b0 = ch[0][0], b1 = ch[0][1], b4 = ch[0][4], b5 = ch[0][5], b6 = ch[0][6];
        float best = iou_a[0];
        if (iou_a[1] > best) {
            best = iou_a[1];
            b0 = ch[1][0]; b1 = ch[1][1]; b4 = ch[1][4]; b5 = ch[1][5]; b6 = ch[1][6];
        }
        if (iou_a[2] > best) {
            best = iou_a[2];
            b0 = ch[2][0]; b1 = ch[2][1]; b4 = ch[2][4]; b5 = ch[2][5]; b6 = ch[2][6];
        }

        // NOTE: wh_loss intentionally reuses indices 0/1 (x/y), replicating
        // the reference bit-exactly.
        const float dx = l0 - b0;
        const float dy = l1 - b1;
        const float xy_loss = dx * dx + dy * dy;

        const float sx = sqrtf(l0) - sqrtf(b0);
        const float sy = sqrtf(l1) - sqrtf(b1);
        const float wh_loss = sx * sx + sy * sy;

        const float coord_loss = xy_loss + wh_loss;

        const bool has_obj = b4 > CONF_THRESH;

        const float d5 = l5 - b5;
        const float d6 = l6 - b6;
        const float class_loss = has_obj ? (d5 * d5 + d6 * d6) : 0.0f;

        const float dc = l4 - b4;
        const float conf_sq = dc * dc;
        const float conf_loss = has_obj ? conf_sq : NO_OBJECT * conf_sq;

        loss = coord_loss + class_loss + conf_loss;
    }

    // ---- block reduction: warp shuffle, then 25 partials via warp 0 ----
    #pragma unroll
    for (int off = 16; off > 0; off >>= 1)
        loss += __shfl_down_sync(0xFFFFFFFFu, loss, off);

    const int lane = threadIdx.x & 31;
    const int warp = threadIdx.x >> 5;
    if (lane == 0) warp_sums[warp] = loss;
    __syncthreads();

    if (warp == 0) {
        float v = (lane < N_WARPS) ? warp_sums[lane] : 0.0f;
        #pragma unroll
        for (int off = 16; off > 0; off >>= 1)
            v += __shfl_down_sync(0xFFFFFFFFu, v, off);
        if (lane == 0) out[0] = v;
    }
}

extern "C" void kernel_launch(void* const* d_in, const int* in_sizes, int n_in,
                              void* d_out, int out_size)
{
    const float* pred  = (const float*)d_in[0];
    const float* label = (const float*)d_in[1];
    float* out = (float*)d_out;
    yolo_loss_kernel<<<1, N_THREADS>>>(pred, label, out);
}

// round 5
// speedup vs baseline: 1.2087x; 1.1783x over previous
#include <cuda_runtime.h>

#define N_CELLS   776
#define N_ANCHORS 3
#define N_CH      7
#define N_THREADS 1024
#define CONF_THRESH 0.8f
#define NO_OBJECT   0.5f

__global__ void __launch_bounds__(N_THREADS, 1)
yolo_loss_kernel(const float* __restrict__ pred,
                 const float* __restrict__ label,
                 float* __restrict__ out)
{
    __shared__ float warp_sums[32];

    const int cell = threadIdx.x;
    float loss = 0.0f;

    if (cell < N_CELLS) {
        const float* base = pred + cell * (N_ANCHORS * N_CH);

        // Front-batch ALL loads (21 pred + 7 label): one latency exposure,
        // MLP ~28, then pure register compute.
        float ch[N_ANCHORS][N_CH];
        #pragma unroll
        for (int a = 0; a < N_ANCHORS; a++)
            #pragma unroll
            for (int c = 0; c < N_CH; c++)
                ch[a][c] = base[a * N_CH + c];

        const float l0 = label[0], l1 = label[1], l2 = label[2], l3 = label[3];
        const float l4 = label[4], l5 = label[5], l6 = label[6];

        const float lx0 = l0 - l2 * 0.5f;
        const float ly0 = l1 - l3 * 0.5f;
        const float lx1 = l0 + l2 * 0.5f;
        const float ly1 = l1 + l3 * 0.5f;
        const float area_b = fabsf(l2 * l3);

        // IoU numerators/denominators only — iou value itself is never used
        // by the loss, only the argmax. den > 0 always (inter <= min area).
        float num[N_ANCHORS], den[N_ANCHORS];
        #pragma unroll
        for (int a = 0; a < N_ANCHORS; a++) {
            const float px = ch[a][0];
            const float py = ch[a][1];
            const float pw = ch[a][2];
            const float ph = ch[a][3];

            const float ax = fmaxf(px - pw * 0.5f, lx0);
            const float ay = fmaxf(py - ph * 0.5f, ly0);
            const float bx = fminf(px + pw * 0.5f, lx1);
            const float by = fminf(py + ph * 0.5f, ly1);

            const float inter = fabsf(fmaxf(bx - ax, 0.0f) * fmaxf(by - ay, 0.0f));
            const float area_a = fabsf(pw * ph);
            num[a] = inter;
            den[a] = area_a + area_b - inter;
        }

        // Division-free argmax, first-max tie-break (strict >):
        //   num[j]/den[j] > num[i]/den[i]  <=>  num[j]*den[i] > num[i]*den[j]
        float b0 = ch[0][0], b1 = ch[0][1], b4 = ch[0][4], b5 = ch[0][5], b6 = ch[0][6];
        float bn = num[0], bd = den[0];
        if (num[1] * bd > bn * den[1]) {
            bn = num[1]; bd = den[1];
            b0 = ch[1][0]; b1 = ch[1][1]; b4 = ch[1][4]; b5 = ch[1][5]; b6 = ch[1][6];
        }
        if (num[2] * bd > bn * den[2]) {
            b0 = ch[2][0]; b1 = ch[2][1]; b4 = ch[2][4]; b5 = ch[2][5]; b6 = ch[2][6];
        }

        // NOTE: wh_loss intentionally reuses indices 0/1 (x/y), replicating
        // the reference bit-exactly.
        const float dx = l0 - b0;
        const float dy = l1 - b1;
        const float xy_loss = dx * dx + dy * dy;

        const float sx = sqrtf(l0) - sqrtf(b0);
        const float sy = sqrtf(l1) - sqrtf(b1);
        const float wh_loss = sx * sx + sy * sy;

        const float coord_loss = xy_loss + wh_loss;

        const bool has_obj = b4 > CONF_THRESH;

        const float d5 = l5 - b5;
        const float d6 = l6 - b6;
        const float class_loss = has_obj ? (d5 * d5 + d6 * d6) : 0.0f;

        const float dc = l4 - b4;
        const float conf_sq = dc * dc;
        const float conf_loss = has_obj ? conf_sq : NO_OBJECT * conf_sq;

        loss = coord_loss + class_loss + conf_loss;
    }

    // ---- block reduction: warp shuffle, then 32 partials via warp 0 ----
    #pragma unroll
    for (int off = 16; off > 0; off >>= 1)
        loss += __shfl_down_sync(0xFFFFFFFFu, loss, off);

    const int lane = threadIdx.x & 31;
    const int warp = threadIdx.x >> 5;
    if (lane == 0) warp_sums[warp] = loss;
    __syncthreads();

    if (warp == 0) {
        float v = warp_sums[lane];   // exactly 32 warps at blockDim=1024
        #pragma unroll
        for (int off = 16; off > 0; off >>= 1)
            v += __shfl_down_sync(0xFFFFFFFFu, v, off);
        if (lane == 0) out[0] = v;
    }
}

extern "C" void kernel_launch(void* const* d_in, const int* in_sizes, int n_in,
                              void* d_out, int out_size)
{
    const float* pred  = (const float*)d_in[0];
    const float* label = (const float*)d_in[1];
    float* out = (float*)d_out;
    yolo_loss_kernel<<<1, N_THREADS>>>(pred, label, out);
}